// round 4
// baseline (speedup 1.0000x reference)
#include <cuda_runtime.h>
#include <cuda_bf16.h>
#include <cstdint>

#define C_DIM 1000
#define C_VEC 250            // C_DIM / 4
#define VPT 8                // ceil(C_VEC / 32)
#define ROWS_PER_CTA 8
#define NTHREADS (ROWS_PER_CTA * 32)

__device__ float        g_scratch = 0.0f;
__device__ unsigned int g_count   = 0;

__global__ __launch_bounds__(NTHREADS, 2)   // allow ~128 regs: keep all 16 float4 loads resident
void ranking_loss_kernel(const float* __restrict__ logits,
                         const float* __restrict__ target,
                         float* __restrict__ out,
                         int B) {
    const int lane = threadIdx.x & 31;
    const int wid  = threadIdx.x >> 5;
    const int row  = blockIdx.x * ROWS_PER_CTA + wid;

    const float4* tg = reinterpret_cast<const float4*>(target + (size_t)row * C_DIM);
    const float4* lg = reinterpret_cast<const float4*>(logits + (size_t)row * C_DIM);

    const float NEG_INF = -3.402823466e+38f;

    // ---- Issue ALL loads up front (no data dependency between arrays):
    //      8 target + 8 logits float4 per lane -> MLP_p1 ~ 16 ----
    float4 t[VPT];
    float4 l[VPT];
    #pragma unroll
    for (int k = 0; k < VPT; k++) {
        int v = lane + 32 * k;
        if (v < C_VEC) t[k] = tg[v];
        else           t[k] = make_float4(NEG_INF, NEG_INF, NEG_INF, NEG_INF);
    }
    #pragma unroll
    for (int k = 0; k < VPT; k++) {
        int v = lane + 32 * k;
        if (v < C_VEC) l[k] = lg[v];
        else           l[k] = make_float4(NEG_INF, NEG_INF, NEG_INF, NEG_INF); // guarded out below
    }

    // ---- Local argmax over target (first-max semantics; strided layout
    //      means within a lane, increasing k/base = increasing index) ----
    float bmax = NEG_INF;
    int   bidx = 0x7fffffff;
    #pragma unroll
    for (int k = 0; k < VPT; k++) {
        int base = (lane + 32 * k) * 4;
        if (t[k].x > bmax) { bmax = t[k].x; bidx = base + 0; }
        if (t[k].y > bmax) { bmax = t[k].y; bidx = base + 1; }
        if (t[k].z > bmax) { bmax = t[k].z; bidx = base + 2; }
        if (t[k].w > bmax) { bmax = t[k].w; bidx = base + 3; }
    }

    // ---- Warp argmax reduce (butterfly; (max, min-index) is assoc+comm) ----
    #pragma unroll
    for (int o = 16; o > 0; o >>= 1) {
        float ov = __shfl_xor_sync(0xffffffffu, bmax, o);
        int   oi = __shfl_xor_sync(0xffffffffu, bidx, o);
        if (ov > bmax || (ov == bmax && oi < bidx)) { bmax = ov; bidx = oi; }
    }
    const int label = bidx;

    // x1 = logits[row][label]: extract from the already-loaded registers via
    // shuffle — the owning lane is (label/4) % 32, the vec slot is (label/4)/32.
    const int  lvec   = label >> 2;          // float4 index
    const int  owner  = lvec & 31;           // lane holding it
    const int  slot   = lvec >> 5;           // which l[k]
    const int  comp   = label & 3;
    float x1cand = 0.0f;
    {
        // select component from l[slot] on every lane, then shuffle from owner
        float4 lv;
        switch (slot) {                      // slot is warp-uniform? NO — label is
            case 0: lv = l[0]; break;        // warp-uniform, so slot/owner/comp are
            case 1: lv = l[1]; break;        // uniform too (post-reduce). Safe.
            case 2: lv = l[2]; break;
            case 3: lv = l[3]; break;
            case 4: lv = l[4]; break;
            case 5: lv = l[5]; break;
            case 6: lv = l[6]; break;
            default: lv = l[7]; break;
        }
        float c = (comp == 0) ? lv.x : (comp == 1) ? lv.y : (comp == 2) ? lv.z : lv.w;
        x1cand = __shfl_sync(0xffffffffu, c, owner);
    }
    const float x1 = x1cand;

    const float inv  = 1.0f / (float)(C_DIM - 1);
    const float labf = (float)label;

    // ---- Hinge sum. margin(0)=1.0 (neg term, NEG_MARGIN=1 folds in),
    //      margin(j)=|label-j|/(C-1) for j>=1. ----
    float acc = 0.0f;
    #pragma unroll
    for (int k = 0; k < VPT; k++) {
        int v = lane + 32 * k;
        if (v < C_VEC) {
            float jf = (float)(v * 4);
            float m0 = (v == 0 && lane == 0) ? 1.0f : fabsf(labf - jf) * inv;
            float m1 = fabsf(labf - (jf + 1.0f)) * inv;
            float m2 = fabsf(labf - (jf + 2.0f)) * inv;
            float m3 = fabsf(labf - (jf + 3.0f)) * inv;
            acc += fmaxf(0.0f, l[k].x - x1 + m0);
            acc += fmaxf(0.0f, l[k].y - x1 + m1);
            acc += fmaxf(0.0f, l[k].z - x1 + m2);
            acc += fmaxf(0.0f, l[k].w - x1 + m3);
        }
    }

    // ---- Warp sum reduce ----
    #pragma unroll
    for (int o = 16; o > 0; o >>= 1)
        acc += __shfl_xor_sync(0xffffffffu, acc, o);

    // per-row contribution (zero when label == 0), pre-scaled by 1/B
    float row_val = (label != 0) ? acc * (1.0f / (float)B) : 0.0f;

    // ---- CTA partial reduce in smem, single atomic per CTA ----
    __shared__ float s_sum[ROWS_PER_CTA];
    if (lane == 0) s_sum[wid] = row_val;
    __syncthreads();

    if (threadIdx.x == 0) {
        float cta = 0.0f;
        #pragma unroll
        for (int w = 0; w < ROWS_PER_CTA; w++) cta += s_sum[w];
        atomicAdd(&g_scratch, cta);
        __threadfence();
        unsigned int done = atomicAdd(&g_count, 1u);
        if (done == gridDim.x - 1) {
            // last CTA: all prior g_scratch adds visible (fence + count order)
            float total = *((volatile float*)&g_scratch);
            out[0] = total;
            g_scratch = 0.0f;   // reset for next graph replay
            g_count   = 0u;
            __threadfence();
        }
    }
}

extern "C" void kernel_launch(void* const* d_in, const int* in_sizes, int n_in,
                              void* d_out, int out_size) {
    const float* logits = (const float*)d_in[0];
    const float* target = (const float*)d_in[1];
    float* out = (float*)d_out;
    const int B = in_sizes[0] / C_DIM;       // 16384
    const int grid = B / ROWS_PER_CTA;       // 2048

    ranking_loss_kernel<<<grid, NTHREADS>>>(logits, target, out, B);
}

// round 5
// speedup vs baseline: 1.0654x; 1.0654x over previous
#include <cuda_runtime.h>
#include <cuda_bf16.h>
#include <cstdint>

#define C_DIM 1000
#define C_VEC 250            // C_DIM / 4
#define VPT 8                // ceil(C_VEC / 32)
#define ROWS_PER_CTA 8
#define NTHREADS (ROWS_PER_CTA * 32)

__device__ float        g_scratch = 0.0f;
__device__ unsigned int g_count   = 0;

__global__ __launch_bounds__(NTHREADS, 5)   // 51-reg cap: one 8xfloat4 batch fits, no giant blowup
void ranking_loss_kernel(const float* __restrict__ logits,
                         const float* __restrict__ target,
                         float* __restrict__ out,
                         int B) {
    const int lane = threadIdx.x & 31;
    const int wid  = threadIdx.x >> 5;
    const int row  = blockIdx.x * ROWS_PER_CTA + wid;

    const float4* tg = reinterpret_cast<const float4*>(target + (size_t)row * C_DIM);
    const float4* lg = reinterpret_cast<const float4*>(logits + (size_t)row * C_DIM);

    const float NEG_INF = -3.402823466e+38f;

    // ================= Phase 1: target scan + argmax =================
    float bmax = NEG_INF;
    int   bidx = 0x7fffffff;
    {
        float4 t[VPT];                      // 32 regs, released after this scope
        #pragma unroll
        for (int k = 0; k < VPT; k++) {
            int v = lane + 32 * k;
            if (v < C_VEC) t[k] = tg[v];
            else           t[k] = make_float4(NEG_INF, NEG_INF, NEG_INF, NEG_INF);
        }
        #pragma unroll
        for (int k = 0; k < VPT; k++) {
            int base = (lane + 32 * k) * 4;
            if (t[k].x > bmax) { bmax = t[k].x; bidx = base + 0; }
            if (t[k].y > bmax) { bmax = t[k].y; bidx = base + 1; }
            if (t[k].z > bmax) { bmax = t[k].z; bidx = base + 2; }
            if (t[k].w > bmax) { bmax = t[k].w; bidx = base + 3; }
        }
    }
    // warp argmax reduce (butterfly; (max, min-index) is assoc+comm)
    #pragma unroll
    for (int o = 16; o > 0; o >>= 1) {
        float ov = __shfl_xor_sync(0xffffffffu, bmax, o);
        int   oi = __shfl_xor_sync(0xffffffffu, bidx, o);
        if (ov > bmax || (ov == bmax && oi < bidx)) { bmax = ov; bidx = oi; }
    }
    const int label = bidx;

    // ================= Phase 2: logits scan + hinge ==================
    float4 l[VPT];                          // reuses phase-1 registers
    #pragma unroll
    for (int k = 0; k < VPT; k++) {
        int v = lane + 32 * k;
        if (v < C_VEC) l[k] = lg[v];
        else           l[k] = make_float4(NEG_INF, NEG_INF, NEG_INF, NEG_INF); // guarded out below
    }

    // x1 = logits[row][label], extracted from registers via shuffle.
    // label is warp-uniform post-reduce, so slot/owner/comp are uniform.
    const int lvec  = label >> 2;
    const int owner = lvec & 31;
    const int slot  = lvec >> 5;
    const int comp  = label & 3;
    float x1;
    {
        float4 lv;
        switch (slot) {
            case 0: lv = l[0]; break;
            case 1: lv = l[1]; break;
            case 2: lv = l[2]; break;
            case 3: lv = l[3]; break;
            case 4: lv = l[4]; break;
            case 5: lv = l[5]; break;
            case 6: lv = l[6]; break;
            default: lv = l[7]; break;
        }
        float c = (comp == 0) ? lv.x : (comp == 1) ? lv.y : (comp == 2) ? lv.z : lv.w;
        x1 = __shfl_sync(0xffffffffu, c, owner);
    }

    const float inv  = 1.0f / (float)(C_DIM - 1);
    const float labf = (float)label;

    // hinge sum: margin(0)=1.0 (neg term, NEG_MARGIN=1 folds in exactly),
    // margin(j)=|label-j|/(C-1) for j>=1.
    float acc = 0.0f;
    #pragma unroll
    for (int k = 0; k < VPT; k++) {
        int v = lane + 32 * k;
        if (v < C_VEC) {
            float jf = (float)(v * 4);
            float m0 = (v == 0 && lane == 0) ? 1.0f : fabsf(labf - jf) * inv;
            float m1 = fabsf(labf - (jf + 1.0f)) * inv;
            float m2 = fabsf(labf - (jf + 2.0f)) * inv;
            float m3 = fabsf(labf - (jf + 3.0f)) * inv;
            acc += fmaxf(0.0f, l[k].x - x1 + m0);
            acc += fmaxf(0.0f, l[k].y - x1 + m1);
            acc += fmaxf(0.0f, l[k].z - x1 + m2);
            acc += fmaxf(0.0f, l[k].w - x1 + m3);
        }
    }

    // warp sum reduce
    #pragma unroll
    for (int o = 16; o > 0; o >>= 1)
        acc += __shfl_xor_sync(0xffffffffu, acc, o);

    // per-row contribution (zero when label == 0), pre-scaled by 1/B
    float row_val = (label != 0) ? acc * (1.0f / (float)B) : 0.0f;

    // ---- CTA partial reduce in smem, single atomic per CTA ----
    __shared__ float s_sum[ROWS_PER_CTA];
    if (lane == 0) s_sum[wid] = row_val;
    __syncthreads();

    if (threadIdx.x == 0) {
        float cta = 0.0f;
        #pragma unroll
        for (int w = 0; w < ROWS_PER_CTA; w++) cta += s_sum[w];
        atomicAdd(&g_scratch, cta);
        __threadfence();
        unsigned int done = atomicAdd(&g_count, 1u);
        if (done == gridDim.x - 1) {
            // last CTA: all prior g_scratch adds visible (fence + count order)
            float total = *((volatile float*)&g_scratch);
            out[0] = total;
            g_scratch = 0.0f;   // reset for next graph replay
            g_count   = 0u;
            __threadfence();
        }
    }
}

extern "C" void kernel_launch(void* const* d_in, const int* in_sizes, int n_in,
                              void* d_out, int out_size) {
    const float* logits = (const float*)d_in[0];
    const float* target = (const float*)d_in[1];
    float* out = (float*)d_out;
    const int B = in_sizes[0] / C_DIM;       // 16384
    const int grid = B / ROWS_PER_CTA;       // 2048

    ranking_loss_kernel<<<grid, NTHREADS>>>(logits, target, out, B);
}